// round 15
// baseline (speedup 1.0000x reference)
#include <cuda_runtime.h>
#include <cuda_bf16.h>
#include <cfloat>
#include <cstdint>

constexpr int NB  = 16;
constexpr int SEQ = 2048;
constexpr int HD  = 128;
constexpr int TT  = SEQ / 128;            // 16
constexpr int NPAIRS = TT * (TT + 1) / 2; // 136
constexpr int CH  = 4;                    // j-tiles per PV chunk
constexpr int NCHUNK_PAIRS = 40;          // sum over it of ceil((TT-it)/CH)
#define SCALE 0.08838834764831845f

__device__ float g_m[NB * SEQ];
__device__ float g_linv[NB * SEQ];
__device__ float g_pm[(size_t)NB * SEQ * TT];          // per-(row, jt) partial max
__device__ float g_pl[(size_t)NB * SEQ * TT];          // per-(row, jt) partial sumexp
__device__ float g_part[(size_t)CH * NB * SEQ * HD];   // 64 MB O partials

// ---------------- smem layouts ----------------
// scores/stats kernel: 128 rows x 64 bf16 + 8 pad -> 144B stride
constexpr int SA_STRIDE = 144;
constexpr int OFF_AH = 0;
constexpr int OFF_AL = 18432;
constexpr int OFF_BH = 36864;
constexpr int OFF_BL = 55296;
constexpr int SMEM_A_BYTES = 73728;
// fused pv kernel: K persistent 128x128 (272B stride), Q/V half 64x128 shared buf
constexpr int ST = 272;
constexpr int OFF_KH  = 0;
constexpr int OFF_KL  = 34816;
constexpr int OFF_QVH = 69632;
constexpr int OFF_QVL = 87040;
constexpr int SMEM_C_BYTES = 104448;

// ---------------- helpers ----------------
__device__ __forceinline__ uint32_t smem_u32(const void* p) {
    uint32_t a;
    asm("{ .reg .u64 t; cvta.to.shared.u64 t, %1; cvt.u32.u64 %0, t; }"
        : "=r"(a) : "l"(p));
    return a;
}
__device__ __forceinline__ void ldm_x4(uint32_t* r, uint32_t addr) {
    asm volatile("ldmatrix.sync.aligned.m8n8.x4.shared.b16 {%0,%1,%2,%3}, [%4];"
        : "=r"(r[0]), "=r"(r[1]), "=r"(r[2]), "=r"(r[3]) : "r"(addr));
}
__device__ __forceinline__ void ldm_x4_t(uint32_t* r, uint32_t addr) {
    asm volatile("ldmatrix.sync.aligned.m8n8.x4.trans.shared.b16 {%0,%1,%2,%3}, [%4];"
        : "=r"(r[0]), "=r"(r[1]), "=r"(r[2]), "=r"(r[3]) : "r"(addr));
}
__device__ __forceinline__ void mma16816(float* d, const uint32_t* a, const uint32_t* b) {
    asm volatile(
        "mma.sync.aligned.m16n8k16.row.col.f32.bf16.bf16.f32 "
        "{%0,%1,%2,%3}, {%4,%5,%6,%7}, {%8,%9}, {%0,%1,%2,%3};"
        : "+f"(d[0]), "+f"(d[1]), "+f"(d[2]), "+f"(d[3])
        : "r"(a[0]), "r"(a[1]), "r"(a[2]), "r"(a[3]), "r"(b[0]), "r"(b[1]));
}
__device__ __forceinline__ void split2(float x, unsigned short& h, unsigned short& l) {
    __nv_bfloat16 hb = __float2bfloat16(x);
    __nv_bfloat16 lb = __float2bfloat16(x - __bfloat162float(hb));
    h = __bfloat16_as_ushort(hb);
    l = __bfloat16_as_ushort(lb);
}
__device__ __forceinline__ void store_split(char* ph, char* pl, float4 v) {
    unsigned short h0,h1,h2,h3,l0,l1,l2,l3;
    split2(v.x,h0,l0); split2(v.y,h1,l1); split2(v.z,h2,l2); split2(v.w,h3,l3);
    *(uint2*)ph = make_uint2((uint32_t)h0 | ((uint32_t)h1 << 16),
                             (uint32_t)h2 | ((uint32_t)h3 << 16));
    *(uint2*)pl = make_uint2((uint32_t)l0 | ((uint32_t)l1 << 16),
                             (uint32_t)l2 | ((uint32_t)l3 << 16));
}

// ---------------------------------------------------------------------------
// Kernel 1: scores+stats.  Per tile-pair (it, jt>=it, b): QK^T via HMMA bf16x3,
// masked per-row (max, sumexp) partials -> g_pm/g_pl.  NO W write.
// ---------------------------------------------------------------------------
__global__ __launch_bounds__(256, 2) void scores_stats_kernel(
    const float* __restrict__ Qg, const float* __restrict__ Kg)
{
    int t = blockIdx.x, b = blockIdx.y;
    int it = 0;
    while (true) { int len = TT - it; if (t < len) break; t -= len; ++it; }
    int jt = it + t;

    extern __shared__ char smc[];
    uint32_t sb = smem_u32(smc);
    int tid = threadIdx.x, wid = tid >> 5, lane = tid & 31;
    int m_base = (wid & 3) * 32, n_base = (wid >> 2) * 64;

    const float* Kb = Kg + ((size_t)b * SEQ + (size_t)it * 128) * HD;
    const float* Qb = Qg + ((size_t)b * SEQ + (size_t)jt * 128) * HD;

    float acc[2][8][4];
    #pragma unroll
    for (int mt = 0; mt < 2; mt++)
        #pragma unroll
        for (int nt = 0; nt < 8; nt++)
            #pragma unroll
            for (int e = 0; e < 4; e++) acc[mt][nt][e] = 0.f;

    #pragma unroll
    for (int ch = 0; ch < 2; ch++) {
        __syncthreads();
        #pragma unroll
        for (int k = 0; k < 8; k++) {
            int idx = tid + k * 256;
            int r = idx >> 4, c4 = idx & 15;
            float4 kv = *(const float4*)(Kb + r * HD + ch * 64 + c4 * 4);
            float4 qv = *(const float4*)(Qb + r * HD + ch * 64 + c4 * 4);
            store_split(smc + OFF_AH + r * SA_STRIDE + c4 * 8,
                        smc + OFF_AL + r * SA_STRIDE + c4 * 8, kv);
            store_split(smc + OFF_BH + r * SA_STRIDE + c4 * 8,
                        smc + OFF_BL + r * SA_STRIDE + c4 * 8, qv);
        }
        __syncthreads();

        int arow = lane & 15, akg = lane >> 4;
        int nrow = (lane & 7) + ((lane & 16) >> 1);
        int bkg  = (lane >> 3) & 1;
        #pragma unroll
        for (int p = 0; p < 3; p++) {
            uint32_t aO = sb + ((p == 2) ? OFF_AL : OFF_AH);
            uint32_t bO = sb + ((p == 1) ? OFF_BL : OFF_BH);
            #pragma unroll
            for (int ks = 0; ks < 4; ks++) {
                uint32_t a[2][4];
                ldm_x4(a[0], aO + (m_base + arow) * SA_STRIDE + (ks * 16 + akg * 8) * 2);
                ldm_x4(a[1], aO + (m_base + 16 + arow) * SA_STRIDE + (ks * 16 + akg * 8) * 2);
                #pragma unroll
                for (int ntp = 0; ntp < 4; ntp++) {
                    uint32_t bf[4];
                    ldm_x4(bf, bO + (n_base + ntp * 16 + nrow) * SA_STRIDE + (ks * 16 + bkg * 8) * 2);
                    #pragma unroll
                    for (int mt = 0; mt < 2; mt++) {
                        mma16816(acc[mt][ntp * 2],     a[mt], bf);
                        mma16816(acc[mt][ntp * 2 + 1], a[mt], bf + 2);
                    }
                }
            }
        }
    }
    __syncthreads();   // staging smem reuse for reduction

    float* spm = (float*)smc;             // [128][2]
    float* spl = (float*)(smc + 1024);
    int r0 = lane >> 2, c0 = (lane & 3) * 2;
    int wcol = wid >> 2;
    #pragma unroll
    for (int mt = 0; mt < 2; mt++) {
        #pragma unroll
        for (int u = 0; u < 2; u++) {
            int row_l = m_base + mt * 16 + u * 8 + r0;
            int ig = it * 128 + row_l;
            float mloc = -FLT_MAX;
            #pragma unroll
            for (int nt = 0; nt < 8; nt++)
                #pragma unroll
                for (int e = 0; e < 2; e++) {
                    int j = jt * 128 + n_base + nt * 8 + c0 + e;
                    if (jt != it || j >= ig)
                        mloc = fmaxf(mloc, acc[mt][nt][2 * u + e] * SCALE);
                }
            float lloc = 0.f;
            #pragma unroll
            for (int nt = 0; nt < 8; nt++)
                #pragma unroll
                for (int e = 0; e < 2; e++) {
                    int j = jt * 128 + n_base + nt * 8 + c0 + e;
                    if (jt != it || j >= ig)
                        lloc += __expf(acc[mt][nt][2 * u + e] * SCALE - mloc);
                }
            #pragma unroll
            for (int d_ = 1; d_ <= 2; d_ <<= 1) {
                float mo  = __shfl_xor_sync(0xffffffffu, mloc, d_);
                float lo_ = __shfl_xor_sync(0xffffffffu, lloc, d_);
                float mn = fmaxf(mloc, mo);
                lloc = lloc * __expf(mloc - mn) + lo_ * __expf(mo - mn);
                mloc = mn;
            }
            if ((lane & 3) == 0) {
                spm[row_l * 2 + wcol] = mloc;
                spl[row_l * 2 + wcol] = lloc;
            }
        }
    }
    __syncthreads();
    if (tid < 128) {
        float m0 = spm[tid * 2], m1 = spm[tid * 2 + 1];
        float l0 = spl[tid * 2], l1 = spl[tid * 2 + 1];
        float mn = fmaxf(m0, m1);
        float l = l0 * __expf(m0 - mn) + l1 * __expf(m1 - mn);
        size_t idx = ((size_t)b * SEQ + it * 128 + tid) * TT + jt;
        g_pm[idx] = mn;
        g_pl[idx] = l;
    }
}

// ---------------------------------------------------------------------------
// Kernel 2: combine per-row partials -> g_m, g_linv.
// ---------------------------------------------------------------------------
__global__ __launch_bounds__(256) void combine_kernel()
{
    int r = blockIdx.x * 256 + threadIdx.x;     // b*SEQ + i
    int i = r & (SEQ - 1);
    int it = i >> 7;
    float m = -FLT_MAX, l = 0.f;
    for (int jt = it; jt < TT; jt++) {
        float mp = g_pm[(size_t)r * TT + jt];
        float lp = g_pl[(size_t)r * TT + jt];
        float mn = fmaxf(m, mp);
        l = l * __expf(m - mn) + lp * __expf(mp - mn);
        m = mn;
    }
    g_m[r] = m;
    g_linv[r] = 1.0f / l;
}

// ---------------------------------------------------------------------------
// Kernel 3: zero-fill fully-masked tiles (jt < it) of W.
// ---------------------------------------------------------------------------
__global__ __launch_bounds__(256) void zero_fill_kernel(float* __restrict__ W)
{
    int it = blockIdx.x;
    int b  = blockIdx.y;
    if (it == 0) return;
    size_t base = (size_t)b * SEQ * SEQ + (size_t)it * 128 * SEQ;
    int cols4 = it * 32;
    int total = 128 * cols4;
    float4 z = make_float4(0.f, 0.f, 0.f, 0.f);
    for (int v = threadIdx.x; v < total; v += 256) {
        int row  = v / cols4;
        int col4 = v - row * cols4;
        *(float4*)(W + base + (size_t)row * SEQ + col4 * 4) = z;
    }
}

// ---------------------------------------------------------------------------
// Kernel 4: fused QK+softmax+W-write+PV.  Per (it, chunk, b):
// recompute S per jt in acc regs, exp-normalize, write final W, repack C-frag
// -> A-frag (hi/lo bf16), PV MMA accumulating O over the chunk's jts.
// ---------------------------------------------------------------------------
__global__ __launch_bounds__(256, 2) void fused_pv_kernel(
    const float* __restrict__ Qg, const float* __restrict__ Kg,
    const float* __restrict__ Vg, float* __restrict__ Wg)
{
    int t = blockIdx.x, b = blockIdx.y;
    int it = 0;
    while (true) { int nc = (TT - it + CH - 1) / CH; if (t < nc) break; t -= nc; ++it; }
    int chunk = t;
    int jt0 = it + chunk * CH;
    int jt1 = min(jt0 + CH, TT);

    extern __shared__ char smc[];
    uint32_t sb = smem_u32(smc);
    int tid = threadIdx.x, wid = tid >> 5, lane = tid & 31;
    int m_base = wid * 16;                 // each warp: 16 rows x full 128 cols

    // stage K persistent (rows i, cols d), hi/lo split
    const float* Kb = Kg + ((size_t)b * SEQ + (size_t)it * 128) * HD;
    #pragma unroll
    for (int k = 0; k < 16; k++) {
        int idx = tid + k * 256;
        int r = idx >> 5, c4 = idx & 31;
        float4 v = *(const float4*)(Kb + r * HD + c4 * 4);
        store_split(smc + OFF_KH + r * ST + c4 * 8,
                    smc + OFF_KL + r * ST + c4 * 8, v);
    }

    int r0 = lane >> 2, c0 = (lane & 3) * 2;
    int i0 = it * 128 + m_base + r0;
    float m0  = g_m[b * SEQ + i0],     li0 = g_linv[b * SEQ + i0];
    float m1  = g_m[b * SEQ + i0 + 8], li1 = g_linv[b * SEQ + i0 + 8];

    float o[16][4];
    #pragma unroll
    for (int nt = 0; nt < 16; nt++)
        #pragma unroll
        for (int e = 0; e < 4; e++) o[nt][e] = 0.f;

    int arow = lane & 15, akg = lane >> 4;
    int nrow = (lane & 7) + ((lane & 16) >> 1), bkg = (lane >> 3) & 1;
    int jrow = (lane & 7) + (lane & 8), dcol = (lane >> 4) * 8;
    size_t Wbb = (size_t)b * SEQ * SEQ;

    for (int jt = jt0; jt < jt1; jt++) {
        #pragma unroll
        for (int nh = 0; nh < 2; nh++) {
            __syncthreads();
            // stage Q rows [jt*128 + nh*64, +64)
            const float* Qb = Qg + ((size_t)b * SEQ + (size_t)jt * 128 + nh * 64) * HD;
            #pragma unroll
            for (int k = 0; k < 8; k++) {
                int idx = tid + k * 256;
                int r = idx >> 5, c4 = idx & 31;
                float4 v = *(const float4*)(Qb + r * HD + c4 * 4);
                store_split(smc + OFF_QVH + r * ST + c4 * 8,
                            smc + OFF_QVL + r * ST + c4 * 8, v);
            }
            __syncthreads();

            // QK^T MMA: S half (16 rows x 64 cols per warp)
            float s[8][4];
            #pragma unroll
            for (int nt = 0; nt < 8; nt++)
                #pragma unroll
                for (int e = 0; e < 4; e++) s[nt][e] = 0.f;
            #pragma unroll
            for (int p = 0; p < 3; p++) {
                uint32_t aO = sb + ((p == 2) ? OFF_KL : OFF_KH);
                uint32_t bO = sb + ((p == 1) ? OFF_QVL : OFF_QVH);
                #pragma unroll
                for (int ks = 0; ks < 8; ks++) {
                    uint32_t a[4];
                    ldm_x4(a, aO + (m_base + arow) * ST + (ks * 16 + akg * 8) * 2);
                    #pragma unroll
                    for (int ntp = 0; ntp < 4; ntp++) {
                        uint32_t bf[4];
                        ldm_x4(bf, bO + (ntp * 16 + nrow) * ST + (ks * 16 + bkg * 8) * 2);
                        mma16816(s[ntp * 2],     a, bf);
                        mma16816(s[ntp * 2 + 1], a, bf + 2);
                    }
                }
            }

            // normalize -> w, write final W, repack C-frag into A-frag hi/lo
            uint32_t ph[16], plo[16];
            #pragma unroll
            for (int nt = 0; nt < 8; nt++) {
                int jg = jt * 128 + nh * 64 + nt * 8 + c0;
                float w0 = __expf(s[nt][0] * SCALE - m0) * li0;
                float w1 = __expf(s[nt][1] * SCALE - m0) * li0;
                float w2 = __expf(s[nt][2] * SCALE - m1) * li1;
                float w3 = __expf(s[nt][3] * SCALE - m1) * li1;
                if (jt == it) {
                    if (jg     < i0)     w0 = 0.f;
                    if (jg + 1 < i0)     w1 = 0.f;
                    if (jg     < i0 + 8) w2 = 0.f;
                    if (jg + 1 < i0 + 8) w3 = 0.f;
                }
                *(float2*)(Wg + Wbb + (size_t)i0 * SEQ + jg)       = make_float2(w0, w1);
                *(float2*)(Wg + Wbb + (size_t)(i0 + 8) * SEQ + jg) = make_float2(w2, w3);
                unsigned short h0,h1,h2,h3,q0,q1,q2,q3;
                split2(w0,h0,q0); split2(w1,h1,q1); split2(w2,h2,q2); split2(w3,h3,q3);
                int at = nt >> 1, sl = (nt & 1) * 2;
                ph[at * 4 + sl]     = (uint32_t)h0 | ((uint32_t)h1 << 16);
                ph[at * 4 + sl + 1] = (uint32_t)h2 | ((uint32_t)h3 << 16);
                plo[at * 4 + sl]     = (uint32_t)q0 | ((uint32_t)q1 << 16);
                plo[at * 4 + sl + 1] = (uint32_t)q2 | ((uint32_t)q3 << 16);
            }

            __syncthreads();
            // stage V rows [jt*128 + nh*64, +64) into same buffer
            const float* Vb = Vg + ((size_t)b * SEQ + (size_t)jt * 128 + nh * 64) * HD;
            #pragma unroll
            for (int k = 0; k < 8; k++) {
                int idx = tid + k * 256;
                int r = idx >> 5, c4 = idx & 31;
                float4 v = *(const float4*)(Vb + r * HD + c4 * 4);
                store_split(smc + OFF_QVH + r * ST + c4 * 8,
                            smc + OFF_QVL + r * ST + c4 * 8, v);
            }
            __syncthreads();

            // PV MMA: O += w * V  (k = j-local 64, n = d 128)
            #pragma unroll
            for (int p = 0; p < 3; p++) {
                const uint32_t* ap = (p == 2) ? plo : ph;
                uint32_t bO = sb + ((p == 1) ? OFF_QVL : OFF_QVH);
                #pragma unroll
                for (int ks = 0; ks < 4; ks++) {
                    #pragma unroll
                    for (int ntp = 0; ntp < 8; ntp++) {
                        uint32_t bf[4];
                        ldm_x4_t(bf, bO + (ks * 16 + jrow) * ST + (ntp * 16 + dcol) * 2);
                        mma16816(o[ntp * 2],     ap + ks * 4, bf);
                        mma16816(o[ntp * 2 + 1], ap + ks * 4, bf + 2);
                    }
                }
            }
        }
    }

    // write partial O tile
    float* pb = g_part + (((size_t)chunk * NB + b) * SEQ) * HD;
    #pragma unroll
    for (int nt = 0; nt < 16; nt++) {
        int d = nt * 8 + c0;
        *(float2*)(pb + (size_t)i0 * HD + d)       = make_float2(o[nt][0], o[nt][1]);
        *(float2*)(pb + (size_t)(i0 + 8) * HD + d) = make_float2(o[nt][2], o[nt][3]);
    }
}

// ---------------------------------------------------------------------------
// Kernel 5: reduce partials into O.
// ---------------------------------------------------------------------------
__global__ __launch_bounds__(256) void reduce_kernel(float* __restrict__ O)
{
    int idx = blockIdx.x * 256 + threadIdx.x;
    size_t base = (size_t)idx * 4;
    int row = (int)(base >> 7);
    int i   = row & (SEQ - 1);
    int it  = i >> 7;
    int nc  = (TT - it + CH - 1) / CH;

    float4 acc = make_float4(0.f, 0.f, 0.f, 0.f);
    for (int cix = 0; cix < nc; cix++) {
        const float4 p = *(const float4*)(g_part + (size_t)cix * NB * SEQ * HD + base);
        acc.x += p.x; acc.y += p.y; acc.z += p.z; acc.w += p.w;
    }
    *(float4*)(O + base) = acc;
}

// ---------------------------------------------------------------------------
extern "C" void kernel_launch(void* const* d_in, const int* in_sizes, int n_in,
                              void* d_out, int out_size)
{
    const float* Q = (const float*)d_in[0];
    const float* K = (const float*)d_in[1];
    const float* V = (const float*)d_in[2];
    float* O = (float*)d_out;                              // [NB, SEQ, HD]
    float* W = (float*)d_out + (size_t)NB * SEQ * HD;      // [NB, SEQ, SEQ]

    cudaFuncSetAttribute(scores_stats_kernel, cudaFuncAttributeMaxDynamicSharedMemorySize, SMEM_A_BYTES);
    cudaFuncSetAttribute(fused_pv_kernel,     cudaFuncAttributeMaxDynamicSharedMemorySize, SMEM_C_BYTES);

    scores_stats_kernel<<<dim3(NPAIRS, NB), 256, SMEM_A_BYTES>>>(Q, K);
    combine_kernel<<<NB * SEQ / 256, 256>>>();
    zero_fill_kernel<<<dim3(TT, NB), 256>>>(W);
    fused_pv_kernel<<<dim3(NCHUNK_PAIRS, NB), 256, SMEM_C_BYTES>>>(Q, K, V, W);
    reduce_kernel<<<(NB * SEQ * HD / 4) / 256, 256>>>(O);
}

// round 16
// speedup vs baseline: 1.4785x; 1.4785x over previous
#include <cuda_runtime.h>
#include <cuda_bf16.h>
#include <cuda_fp16.h>
#include <cfloat>
#include <cstdint>

constexpr int NB  = 16;
constexpr int SEQ = 2048;
constexpr int HD  = 128;
constexpr int TT  = SEQ / 128;            // 16
constexpr int NPAIRS = TT * (TT + 1) / 2; // 136
constexpr int CH  = 4;                    // j-tiles per PV chunk
constexpr int NCHUNK_PAIRS = 40;          // sum over it of ceil((TT-it)/CH)
#define SCALE 0.08838834764831845f

__device__ float g_m[NB * SEQ];
__device__ float g_linv[NB * SEQ];
__device__ float g_pm[(size_t)NB * SEQ * TT];          // per-(row, jt) partial max
__device__ float g_pl[(size_t)NB * SEQ * TT];          // per-(row, jt) partial sumexp
__device__ float g_part[(size_t)CH * NB * SEQ * HD];   // 64 MB O partials

// ---------------- smem layouts ----------------
// scores kernel: 128 rows x 64 bf16 + pad -> 144B stride (hi/lo x A/B)
constexpr int SA_STRIDE = 144;
constexpr int OFF_AH = 0;
constexpr int OFF_AL = 18432;
constexpr int OFF_BH = 36864;
constexpr int OFF_BL = 55296;
constexpr int SMEM_A_BYTES = 73728;
// pv kernel (fp16 single-pass): W 128x64 fp16 (144B stride), V 64x128 fp16 (272B stride)
constexpr int OFF_WH = 0;                 // 18432 bytes
constexpr int SV_STRIDE = 272;
constexpr int OFF_VH = 18432;             // 64*272 = 17408 bytes
constexpr int SMEM_P_BYTES = 35840;

// ---------------- helpers ----------------
__device__ __forceinline__ uint32_t smem_u32(const void* p) {
    uint32_t a;
    asm("{ .reg .u64 t; cvta.to.shared.u64 t, %1; cvt.u32.u64 %0, t; }"
        : "=r"(a) : "l"(p));
    return a;
}
__device__ __forceinline__ void ldm_x4(uint32_t* r, uint32_t addr) {
    asm volatile("ldmatrix.sync.aligned.m8n8.x4.shared.b16 {%0,%1,%2,%3}, [%4];"
        : "=r"(r[0]), "=r"(r[1]), "=r"(r[2]), "=r"(r[3]) : "r"(addr));
}
__device__ __forceinline__ void ldm_x4_t(uint32_t* r, uint32_t addr) {
    asm volatile("ldmatrix.sync.aligned.m8n8.x4.trans.shared.b16 {%0,%1,%2,%3}, [%4];"
        : "=r"(r[0]), "=r"(r[1]), "=r"(r[2]), "=r"(r[3]) : "r"(addr));
}
__device__ __forceinline__ void mma_bf16(float* d, const uint32_t* a, const uint32_t* b) {
    asm volatile(
        "mma.sync.aligned.m16n8k16.row.col.f32.bf16.bf16.f32 "
        "{%0,%1,%2,%3}, {%4,%5,%6,%7}, {%8,%9}, {%0,%1,%2,%3};"
        : "+f"(d[0]), "+f"(d[1]), "+f"(d[2]), "+f"(d[3])
        : "r"(a[0]), "r"(a[1]), "r"(a[2]), "r"(a[3]), "r"(b[0]), "r"(b[1]));
}
__device__ __forceinline__ void mma_f16(float* d, const uint32_t* a, const uint32_t* b) {
    asm volatile(
        "mma.sync.aligned.m16n8k16.row.col.f32.f16.f16.f32 "
        "{%0,%1,%2,%3}, {%4,%5,%6,%7}, {%8,%9}, {%0,%1,%2,%3};"
        : "+f"(d[0]), "+f"(d[1]), "+f"(d[2]), "+f"(d[3])
        : "r"(a[0]), "r"(a[1]), "r"(a[2]), "r"(a[3]), "r"(b[0]), "r"(b[1]));
}
__device__ __forceinline__ void split2(float x, unsigned short& h, unsigned short& l) {
    __nv_bfloat16 hb = __float2bfloat16(x);
    __nv_bfloat16 lb = __float2bfloat16(x - __bfloat162float(hb));
    h = __bfloat16_as_ushort(hb);
    l = __bfloat16_as_ushort(lb);
}
__device__ __forceinline__ void store_split(char* ph, char* pl, float4 v) {
    unsigned short h0,h1,h2,h3,l0,l1,l2,l3;
    split2(v.x,h0,l0); split2(v.y,h1,l1); split2(v.z,h2,l2); split2(v.w,h3,l3);
    *(uint2*)ph = make_uint2((uint32_t)h0 | ((uint32_t)h1 << 16),
                             (uint32_t)h2 | ((uint32_t)h3 << 16));
    *(uint2*)pl = make_uint2((uint32_t)l0 | ((uint32_t)l1 << 16),
                             (uint32_t)l2 | ((uint32_t)l3 << 16));
}
__device__ __forceinline__ uint32_t pack_half2(float a, float b) {
    __half2 h = __floats2half2_rn(a, b);
    return *(uint32_t*)&h;
}

// ---------------------------------------------------------------------------
// Kernel 1: scores + stats.  Per tile pair (it, jt>=it, b): QK^T via HMMA
// bf16x3, write raw scaled scores to W, AND per-row masked (max, sumexp)
// partials in-register -> g_pm/g_pl (kills the separate stats pass).
// ---------------------------------------------------------------------------
__global__ __launch_bounds__(256, 2) void scores_stats_kernel(
    const float* __restrict__ Qg, const float* __restrict__ Kg,
    float* __restrict__ Wg)
{
    int t = blockIdx.x, b = blockIdx.y;
    int it = 0;
    while (true) { int len = TT - it; if (t < len) break; t -= len; ++it; }
    int jt = it + t;

    extern __shared__ char smc[];
    uint32_t sb = smem_u32(smc);
    int tid = threadIdx.x, wid = tid >> 5, lane = tid & 31;
    int m_base = (wid & 3) * 32, n_base = (wid >> 2) * 64;

    const float* Kb = Kg + ((size_t)b * SEQ + (size_t)it * 128) * HD;
    const float* Qb = Qg + ((size_t)b * SEQ + (size_t)jt * 128) * HD;

    float acc[2][8][4];
    #pragma unroll
    for (int mt = 0; mt < 2; mt++)
        #pragma unroll
        for (int nt = 0; nt < 8; nt++)
            #pragma unroll
            for (int e = 0; e < 4; e++) acc[mt][nt][e] = 0.f;

    #pragma unroll
    for (int ch = 0; ch < 2; ch++) {
        __syncthreads();
        #pragma unroll
        for (int k = 0; k < 8; k++) {
            int idx = tid + k * 256;
            int r = idx >> 4, c4 = idx & 15;
            float4 kv = *(const float4*)(Kb + r * HD + ch * 64 + c4 * 4);
            float4 qv = *(const float4*)(Qb + r * HD + ch * 64 + c4 * 4);
            store_split(smc + OFF_AH + r * SA_STRIDE + c4 * 8,
                        smc + OFF_AL + r * SA_STRIDE + c4 * 8, kv);
            store_split(smc + OFF_BH + r * SA_STRIDE + c4 * 8,
                        smc + OFF_BL + r * SA_STRIDE + c4 * 8, qv);
        }
        __syncthreads();

        int arow = lane & 15, akg = lane >> 4;
        int nrow = (lane & 7) + ((lane & 16) >> 1);
        int bkg  = (lane >> 3) & 1;
        #pragma unroll
        for (int p = 0; p < 3; p++) {
            uint32_t aO = sb + ((p == 2) ? OFF_AL : OFF_AH);
            uint32_t bO = sb + ((p == 1) ? OFF_BL : OFF_BH);
            #pragma unroll
            for (int ks = 0; ks < 4; ks++) {
                uint32_t a[2][4];
                ldm_x4(a[0], aO + (m_base + arow) * SA_STRIDE + (ks * 16 + akg * 8) * 2);
                ldm_x4(a[1], aO + (m_base + 16 + arow) * SA_STRIDE + (ks * 16 + akg * 8) * 2);
                #pragma unroll
                for (int ntp = 0; ntp < 4; ntp++) {
                    uint32_t bf[4];
                    ldm_x4(bf, bO + (n_base + ntp * 16 + nrow) * SA_STRIDE + (ks * 16 + bkg * 8) * 2);
                    #pragma unroll
                    for (int mt = 0; mt < 2; mt++) {
                        mma_bf16(acc[mt][ntp * 2],     a[mt], bf);
                        mma_bf16(acc[mt][ntp * 2 + 1], a[mt], bf + 2);
                    }
                }
            }
        }
    }

    // epilogue A: write raw scaled scores
    size_t Wbb = (size_t)b * SEQ * SEQ;
    int r0 = lane >> 2, c0 = (lane & 3) * 2;
    #pragma unroll
    for (int mt = 0; mt < 2; mt++) {
        #pragma unroll
        for (int nt = 0; nt < 8; nt++) {
            int i0 = it * 128 + m_base + mt * 16 + r0;
            int j  = jt * 128 + n_base + nt * 8 + c0;
            float* p0 = Wg + Wbb + (size_t)i0 * SEQ + j;
            *(float2*)p0 = make_float2(acc[mt][nt][0] * SCALE, acc[mt][nt][1] * SCALE);
            *(float2*)(p0 + (size_t)8 * SEQ) =
                make_float2(acc[mt][nt][2] * SCALE, acc[mt][nt][3] * SCALE);
        }
    }

    // epilogue B: masked per-row (max, sumexp) partials (smem reuse after sync)
    __syncthreads();
    float* spm = (float*)smc;             // [128][2]
    float* spl = (float*)(smc + 1024);
    int wcol = wid >> 2;
    #pragma unroll
    for (int mt = 0; mt < 2; mt++) {
        #pragma unroll
        for (int u = 0; u < 2; u++) {
            int row_l = m_base + mt * 16 + u * 8 + r0;
            int ig = it * 128 + row_l;
            float mloc = -FLT_MAX;
            #pragma unroll
            for (int nt = 0; nt < 8; nt++)
                #pragma unroll
                for (int e = 0; e < 2; e++) {
                    int j = jt * 128 + n_base + nt * 8 + c0 + e;
                    if (jt != it || j >= ig)
                        mloc = fmaxf(mloc, acc[mt][nt][2 * u + e] * SCALE);
                }
            float lloc = 0.f;
            #pragma unroll
            for (int nt = 0; nt < 8; nt++)
                #pragma unroll
                for (int e = 0; e < 2; e++) {
                    int j = jt * 128 + n_base + nt * 8 + c0 + e;
                    if (jt != it || j >= ig)
                        lloc += __expf(acc[mt][nt][2 * u + e] * SCALE - mloc);
                }
            #pragma unroll
            for (int d_ = 1; d_ <= 2; d_ <<= 1) {
                float mo  = __shfl_xor_sync(0xffffffffu, mloc, d_);
                float lo_ = __shfl_xor_sync(0xffffffffu, lloc, d_);
                float mn = fmaxf(mloc, mo);
                lloc = lloc * __expf(mloc - mn) + lo_ * __expf(mo - mn);
                mloc = mn;
            }
            if ((lane & 3) == 0) {
                spm[row_l * 2 + wcol] = mloc;
                spl[row_l * 2 + wcol] = lloc;
            }
        }
    }
    __syncthreads();
    if (tid < 128) {
        float m0 = spm[tid * 2], m1 = spm[tid * 2 + 1];
        float l0 = spl[tid * 2], l1 = spl[tid * 2 + 1];
        float mn = fmaxf(m0, m1);
        float l = l0 * __expf(m0 - mn) + l1 * __expf(m1 - mn);
        size_t idx = ((size_t)b * SEQ + it * 128 + tid) * TT + jt;
        g_pm[idx] = mn;
        g_pl[idx] = l;
    }
}

// ---------------------------------------------------------------------------
// Kernel 2: combine per-row partials -> g_m, g_linv.
// ---------------------------------------------------------------------------
__global__ __launch_bounds__(256) void combine_kernel()
{
    int r = blockIdx.x * 256 + threadIdx.x;     // b*SEQ + i
    int i = r & (SEQ - 1);
    int it = i >> 7;
    float m = -FLT_MAX, l = 0.f;
    for (int jt = it; jt < TT; jt++) {
        float mp = g_pm[(size_t)r * TT + jt];
        float lp = g_pl[(size_t)r * TT + jt];
        float mn = fmaxf(m, mp);
        l = l * __expf(m - mn) + lp * __expf(mp - mn);
        m = mn;
    }
    g_m[r] = m;
    g_linv[r] = 1.0f / l;
}

// ---------------------------------------------------------------------------
// Kernel 3: zero-fill fully-masked tiles (jt < it) of W.
// ---------------------------------------------------------------------------
__global__ __launch_bounds__(256) void zero_fill_kernel(float* __restrict__ W)
{
    int it = blockIdx.x;
    int b  = blockIdx.y;
    if (it == 0) return;
    size_t base = (size_t)b * SEQ * SEQ + (size_t)it * 128 * SEQ;
    int cols4 = it * 32;
    int total = 128 * cols4;
    float4 z = make_float4(0.f, 0.f, 0.f, 0.f);
    for (int v = threadIdx.x; v < total; v += 256) {
        int row  = v / cols4;
        int col4 = v - row * cols4;
        *(float4*)(W + base + (size_t)row * SEQ + col4 * 4) = z;
    }
}

// ---------------------------------------------------------------------------
// Kernel 4: chunked PV via SINGLE-PASS fp16 HMMA with fused normalize +
// final-W write.  W in [0,1] and V ~ N(0,1) both fit fp16; O error ~3e-4.
// ---------------------------------------------------------------------------
__global__ __launch_bounds__(256, 2) void pv_kernel(
    const float* __restrict__ Vg, float* __restrict__ Wg)
{
    int t = blockIdx.x, b = blockIdx.y;
    int it = 0;
    while (true) { int nc = (TT - it + CH - 1) / CH; if (t < nc) break; t -= nc; ++it; }
    int chunk = t;
    int jt_begin = it + chunk * CH;
    int jt_end   = min(jt_begin + CH, TT);

    extern __shared__ char smc[];
    uint32_t sb = smem_u32(smc);
    int tid = threadIdx.x, wid = tid >> 5, lane = tid & 31;
    int m_base = (wid & 3) * 32, n_base = (wid >> 2) * 64;   // n = d
    size_t Wbb = (size_t)b * SEQ * SEQ;

    float acc[2][8][4];
    #pragma unroll
    for (int mt = 0; mt < 2; mt++)
        #pragma unroll
        for (int nt = 0; nt < 8; nt++)
            #pragma unroll
            for (int e = 0; e < 4; e++) acc[mt][nt][e] = 0.f;

    for (int jt = jt_begin; jt < jt_end; jt++) {
        #pragma unroll
        for (int kc = 0; kc < 2; kc++) {
            __syncthreads();
            // stage normalized W fp16 (cols kc*64..+64), write final W to gmem
            #pragma unroll
            for (int k = 0; k < 8; k++) {
                int idx = tid + k * 256;
                int r = idx >> 4, c4 = idx & 15;
                int ig = it * 128 + r;
                int jg = jt * 128 + kc * 64 + c4 * 4;
                float mm = g_m[b * SEQ + ig];
                float li = g_linv[b * SEQ + ig];
                float* wp = Wg + Wbb + (size_t)ig * SEQ + jg;
                float4 s = *(const float4*)wp;
                float4 w;
                w.x = (jg + 0 >= ig) ? __expf(s.x - mm) * li : 0.f;
                w.y = (jg + 1 >= ig) ? __expf(s.y - mm) * li : 0.f;
                w.z = (jg + 2 >= ig) ? __expf(s.z - mm) * li : 0.f;
                w.w = (jg + 3 >= ig) ? __expf(s.w - mm) * li : 0.f;
                *(float4*)wp = w;
                *(uint2*)(smc + OFF_WH + r * SA_STRIDE + c4 * 8) =
                    make_uint2(pack_half2(w.x, w.y), pack_half2(w.z, w.w));
            }
            // stage V fp16 rows [jt*128+kc*64, +64), row-major [j][d]
            const float* Vb = Vg + ((size_t)b * SEQ + (size_t)jt * 128 + kc * 64) * HD;
            #pragma unroll
            for (int k = 0; k < 8; k++) {
                int idx = tid + k * 256;
                int r = idx >> 5, c4 = idx & 31;
                float4 v = *(const float4*)(Vb + r * HD + c4 * 4);
                *(uint2*)(smc + OFF_VH + r * SV_STRIDE + c4 * 8) =
                    make_uint2(pack_half2(v.x, v.y), pack_half2(v.z, v.w));
            }
            __syncthreads();

            int arow = lane & 15, akg = lane >> 4;
            int jrow = (lane & 7) + (lane & 8);     // trans-B source row (k = j)
            int dcol = (lane >> 4) * 8;
            #pragma unroll
            for (int ks = 0; ks < 4; ks++) {
                uint32_t a[2][4];
                ldm_x4(a[0], sb + OFF_WH + (m_base + arow) * SA_STRIDE + (ks * 16 + akg * 8) * 2);
                ldm_x4(a[1], sb + OFF_WH + (m_base + 16 + arow) * SA_STRIDE + (ks * 16 + akg * 8) * 2);
                #pragma unroll
                for (int ntp = 0; ntp < 4; ntp++) {
                    uint32_t bf[4];
                    ldm_x4_t(bf, sb + OFF_VH + (ks * 16 + jrow) * SV_STRIDE
                                  + (n_base + ntp * 16 + dcol) * 2);
                    #pragma unroll
                    for (int mt = 0; mt < 2; mt++) {
                        mma_f16(acc[mt][ntp * 2],     a[mt], bf);
                        mma_f16(acc[mt][ntp * 2 + 1], a[mt], bf + 2);
                    }
                }
            }
        }
    }

    // write partial O tile
    float* pb = g_part + (((size_t)chunk * NB + b) * SEQ) * HD;
    int r0 = lane >> 2, c0 = (lane & 3) * 2;
    #pragma unroll
    for (int mt = 0; mt < 2; mt++) {
        #pragma unroll
        for (int nt = 0; nt < 8; nt++) {
            int i0 = it * 128 + m_base + mt * 16 + r0;
            int d  = n_base + nt * 8 + c0;
            *(float2*)(pb + (size_t)i0 * HD + d) =
                make_float2(acc[mt][nt][0], acc[mt][nt][1]);
            *(float2*)(pb + (size_t)(i0 + 8) * HD + d) =
                make_float2(acc[mt][nt][2], acc[mt][nt][3]);
        }
    }
}

// ---------------------------------------------------------------------------
// Kernel 5: reduce partials into O.
// ---------------------------------------------------------------------------
__global__ __launch_bounds__(256) void reduce_kernel(float* __restrict__ O)
{
    int idx = blockIdx.x * 256 + threadIdx.x;
    size_t base = (size_t)idx * 4;
    int row = (int)(base >> 7);
    int i   = row & (SEQ - 1);
    int it  = i >> 7;
    int nc  = (TT - it + CH - 1) / CH;

    float4 acc = make_float4(0.f, 0.f, 0.f, 0.f);
    for (int cix = 0; cix < nc; cix++) {
        const float4 p = *(const float4*)(g_part + (size_t)cix * NB * SEQ * HD + base);
        acc.x += p.x; acc.y += p.y; acc.z += p.z; acc.w += p.w;
    }
    *(float4*)(O + base) = acc;
}

// ---------------------------------------------------------------------------
extern "C" void kernel_launch(void* const* d_in, const int* in_sizes, int n_in,
                              void* d_out, int out_size)
{
    const float* Q = (const float*)d_in[0];
    const float* K = (const float*)d_in[1];
    const float* V = (const float*)d_in[2];
    float* O = (float*)d_out;                              // [NB, SEQ, HD]
    float* W = (float*)d_out + (size_t)NB * SEQ * HD;      // [NB, SEQ, SEQ]

    cudaFuncSetAttribute(scores_stats_kernel, cudaFuncAttributeMaxDynamicSharedMemorySize, SMEM_A_BYTES);
    cudaFuncSetAttribute(pv_kernel,           cudaFuncAttributeMaxDynamicSharedMemorySize, SMEM_P_BYTES);

    scores_stats_kernel<<<dim3(NPAIRS, NB), 256, SMEM_A_BYTES>>>(Q, K, W);
    combine_kernel<<<NB * SEQ / 256, 256>>>();
    zero_fill_kernel<<<dim3(TT, NB), 256>>>(W);
    pv_kernel<<<dim3(NCHUNK_PAIRS, NB), 256, SMEM_P_BYTES>>>(V, W);
    reduce_kernel<<<(NB * SEQ * HD / 4) / 256, 256>>>(O);
}

// round 17
// speedup vs baseline: 1.5352x; 1.0384x over previous
#include <cuda_runtime.h>
#include <cuda_bf16.h>
#include <cuda_fp16.h>
#include <cfloat>
#include <cstdint>

constexpr int NB  = 16;
constexpr int SEQ = 2048;
constexpr int HD  = 128;
constexpr int TT  = SEQ / 128;            // 16
constexpr int NPAIRS = TT * (TT + 1) / 2; // 136
constexpr int CH  = 2;                    // j-tiles per PV chunk
constexpr int NCHUNK_PAIRS = 72;          // sum over it of ceil((TT-it)/CH)
constexpr int MAXCH = (TT + CH - 1) / CH; // 8
#define SCALE 0.08838834764831845f

__device__ float g_pm[(size_t)NB * SEQ * TT];          // per-(row, jt) partial max
__device__ float g_pl[(size_t)NB * SEQ * TT];          // per-(row, jt) partial sumexp
__device__ float g_part[(size_t)MAXCH * NB * SEQ * HD];// 128 MB O partials

// ---------------- smem layouts ----------------
// scores kernel: 128 rows x 64 bf16 + pad -> 144B stride (hi/lo x A/B)
constexpr int SA_STRIDE = 144;
constexpr int OFF_AH = 0;
constexpr int OFF_AL = 18432;
constexpr int OFF_BH = 36864;
constexpr int OFF_BL = 55296;
constexpr int SMEM_A_BYTES = 73728;
// pv kernel: W 128x64 fp16 (144B stride), V 64x128 fp16 (272B stride), m/linv
constexpr int OFF_WH = 0;                 // 18432 bytes
constexpr int SV_STRIDE = 272;
constexpr int OFF_VH = 18432;             // 17408 bytes
constexpr int OFF_M  = 35840;             // 512 bytes (128 floats)
constexpr int OFF_LI = 36352;             // 512 bytes
constexpr int SMEM_P_BYTES = 36864;

// ---------------- helpers ----------------
__device__ __forceinline__ uint32_t smem_u32(const void* p) {
    uint32_t a;
    asm("{ .reg .u64 t; cvta.to.shared.u64 t, %1; cvt.u32.u64 %0, t; }"
        : "=r"(a) : "l"(p));
    return a;
}
__device__ __forceinline__ void ldm_x4(uint32_t* r, uint32_t addr) {
    asm volatile("ldmatrix.sync.aligned.m8n8.x4.shared.b16 {%0,%1,%2,%3}, [%4];"
        : "=r"(r[0]), "=r"(r[1]), "=r"(r[2]), "=r"(r[3]) : "r"(addr));
}
__device__ __forceinline__ void ldm_x4_t(uint32_t* r, uint32_t addr) {
    asm volatile("ldmatrix.sync.aligned.m8n8.x4.trans.shared.b16 {%0,%1,%2,%3}, [%4];"
        : "=r"(r[0]), "=r"(r[1]), "=r"(r[2]), "=r"(r[3]) : "r"(addr));
}
__device__ __forceinline__ void mma_bf16(float* d, const uint32_t* a, const uint32_t* b) {
    asm volatile(
        "mma.sync.aligned.m16n8k16.row.col.f32.bf16.bf16.f32 "
        "{%0,%1,%2,%3}, {%4,%5,%6,%7}, {%8,%9}, {%0,%1,%2,%3};"
        : "+f"(d[0]), "+f"(d[1]), "+f"(d[2]), "+f"(d[3])
        : "r"(a[0]), "r"(a[1]), "r"(a[2]), "r"(a[3]), "r"(b[0]), "r"(b[1]));
}
__device__ __forceinline__ void mma_f16(float* d, const uint32_t* a, const uint32_t* b) {
    asm volatile(
        "mma.sync.aligned.m16n8k16.row.col.f32.f16.f16.f32 "
        "{%0,%1,%2,%3}, {%4,%5,%6,%7}, {%8,%9}, {%0,%1,%2,%3};"
        : "+f"(d[0]), "+f"(d[1]), "+f"(d[2]), "+f"(d[3])
        : "r"(a[0]), "r"(a[1]), "r"(a[2]), "r"(a[3]), "r"(b[0]), "r"(b[1]));
}
__device__ __forceinline__ void split2(float x, unsigned short& h, unsigned short& l) {
    __nv_bfloat16 hb = __float2bfloat16(x);
    __nv_bfloat16 lb = __float2bfloat16(x - __bfloat162float(hb));
    h = __bfloat16_as_ushort(hb);
    l = __bfloat16_as_ushort(lb);
}
__device__ __forceinline__ void store_split(char* ph, char* pl, float4 v) {
    unsigned short h0,h1,h2,h3,l0,l1,l2,l3;
    split2(v.x,h0,l0); split2(v.y,h1,l1); split2(v.z,h2,l2); split2(v.w,h3,l3);
    *(uint2*)ph = make_uint2((uint32_t)h0 | ((uint32_t)h1 << 16),
                             (uint32_t)h2 | ((uint32_t)h3 << 16));
    *(uint2*)pl = make_uint2((uint32_t)l0 | ((uint32_t)l1 << 16),
                             (uint32_t)l2 | ((uint32_t)l3 << 16));
}
__device__ __forceinline__ uint32_t pack_half2(float a, float b) {
    __half2 h = __floats2half2_rn(a, b);
    return *(uint32_t*)&h;
}

// ---------------------------------------------------------------------------
// Kernel 1: scores + stats + zero-fill.
//  blocks t <  NPAIRS : tile pair (it, jt>=it): QK^T bf16x3, write raw scaled
//                       scores, per-row masked (max,sumexp) partials.
//  blocks t >= NPAIRS : zero-fill fully-masked row band it = t - NPAIRS.
// ---------------------------------------------------------------------------
__global__ __launch_bounds__(256, 2) void scores_stats_kernel(
    const float* __restrict__ Qg, const float* __restrict__ Kg,
    float* __restrict__ Wg)
{
    int t = blockIdx.x, b = blockIdx.y;
    int tid = threadIdx.x;

    if (t >= NPAIRS) {
        // zero-fill role
        int it = t - NPAIRS;
        if (it == 0) return;
        size_t base = (size_t)b * SEQ * SEQ + (size_t)it * 128 * SEQ;
        int cols4 = it * 32;
        int total = 128 * cols4;
        float4 z = make_float4(0.f, 0.f, 0.f, 0.f);
        for (int v = tid; v < total; v += 256) {
            int row  = v / cols4;
            int col4 = v - row * cols4;
            *(float4*)(Wg + base + (size_t)row * SEQ + col4 * 4) = z;
        }
        return;
    }

    int it = 0;
    while (true) { int len = TT - it; if (t < len) break; t -= len; ++it; }
    int jt = it + t;

    extern __shared__ char smc[];
    uint32_t sb = smem_u32(smc);
    int wid = tid >> 5, lane = tid & 31;
    int m_base = (wid & 3) * 32, n_base = (wid >> 2) * 64;

    const float* Kb = Kg + ((size_t)b * SEQ + (size_t)it * 128) * HD;
    const float* Qb = Qg + ((size_t)b * SEQ + (size_t)jt * 128) * HD;

    float acc[2][8][4];
    #pragma unroll
    for (int mt = 0; mt < 2; mt++)
        #pragma unroll
        for (int nt = 0; nt < 8; nt++)
            #pragma unroll
            for (int e = 0; e < 4; e++) acc[mt][nt][e] = 0.f;

    #pragma unroll
    for (int ch = 0; ch < 2; ch++) {
        __syncthreads();
        #pragma unroll
        for (int k = 0; k < 8; k++) {
            int idx = tid + k * 256;
            int r = idx >> 4, c4 = idx & 15;
            float4 kv = *(const float4*)(Kb + r * HD + ch * 64 + c4 * 4);
            float4 qv = *(const float4*)(Qb + r * HD + ch * 64 + c4 * 4);
            store_split(smc + OFF_AH + r * SA_STRIDE + c4 * 8,
                        smc + OFF_AL + r * SA_STRIDE + c4 * 8, kv);
            store_split(smc + OFF_BH + r * SA_STRIDE + c4 * 8,
                        smc + OFF_BL + r * SA_STRIDE + c4 * 8, qv);
        }
        __syncthreads();

        int arow = lane & 15, akg = lane >> 4;
        int nrow = (lane & 7) + ((lane & 16) >> 1);
        int bkg  = (lane >> 3) & 1;
        #pragma unroll
        for (int p = 0; p < 3; p++) {
            uint32_t aO = sb + ((p == 2) ? OFF_AL : OFF_AH);
            uint32_t bO = sb + ((p == 1) ? OFF_BL : OFF_BH);
            #pragma unroll
            for (int ks = 0; ks < 4; ks++) {
                uint32_t a[2][4];
                ldm_x4(a[0], aO + (m_base + arow) * SA_STRIDE + (ks * 16 + akg * 8) * 2);
                ldm_x4(a[1], aO + (m_base + 16 + arow) * SA_STRIDE + (ks * 16 + akg * 8) * 2);
                #pragma unroll
                for (int ntp = 0; ntp < 4; ntp++) {
                    uint32_t bf[4];
                    ldm_x4(bf, bO + (n_base + ntp * 16 + nrow) * SA_STRIDE + (ks * 16 + bkg * 8) * 2);
                    #pragma unroll
                    for (int mt = 0; mt < 2; mt++) {
                        mma_bf16(acc[mt][ntp * 2],     a[mt], bf);
                        mma_bf16(acc[mt][ntp * 2 + 1], a[mt], bf + 2);
                    }
                }
            }
        }
    }

    // epilogue A: write raw scaled scores
    size_t Wbb = (size_t)b * SEQ * SEQ;
    int r0 = lane >> 2, c0 = (lane & 3) * 2;
    #pragma unroll
    for (int mt = 0; mt < 2; mt++) {
        #pragma unroll
        for (int nt = 0; nt < 8; nt++) {
            int i0 = it * 128 + m_base + mt * 16 + r0;
            int j  = jt * 128 + n_base + nt * 8 + c0;
            float* p0 = Wg + Wbb + (size_t)i0 * SEQ + j;
            *(float2*)p0 = make_float2(acc[mt][nt][0] * SCALE, acc[mt][nt][1] * SCALE);
            *(float2*)(p0 + (size_t)8 * SEQ) =
                make_float2(acc[mt][nt][2] * SCALE, acc[mt][nt][3] * SCALE);
        }
    }

    // epilogue B: masked per-row (max, sumexp) partials (smem reuse after sync)
    __syncthreads();
    float* spm = (float*)smc;             // [128][2]
    float* spl = (float*)(smc + 1024);
    int wcol = wid >> 2;
    #pragma unroll
    for (int mt = 0; mt < 2; mt++) {
        #pragma unroll
        for (int u = 0; u < 2; u++) {
            int row_l = m_base + mt * 16 + u * 8 + r0;
            int ig = it * 128 + row_l;
            float mloc = -FLT_MAX;
            #pragma unroll
            for (int nt = 0; nt < 8; nt++)
                #pragma unroll
                for (int e = 0; e < 2; e++) {
                    int j = jt * 128 + n_base + nt * 8 + c0 + e;
                    if (jt != it || j >= ig)
                        mloc = fmaxf(mloc, acc[mt][nt][2 * u + e] * SCALE);
                }
            float lloc = 0.f;
            #pragma unroll
            for (int nt = 0; nt < 8; nt++)
                #pragma unroll
                for (int e = 0; e < 2; e++) {
                    int j = jt * 128 + n_base + nt * 8 + c0 + e;
                    if (jt != it || j >= ig)
                        lloc += __expf(acc[mt][nt][2 * u + e] * SCALE - mloc);
                }
            #pragma unroll
            for (int d_ = 1; d_ <= 2; d_ <<= 1) {
                float mo  = __shfl_xor_sync(0xffffffffu, mloc, d_);
                float lo_ = __shfl_xor_sync(0xffffffffu, lloc, d_);
                float mn = fmaxf(mloc, mo);
                lloc = lloc * __expf(mloc - mn) + lo_ * __expf(mo - mn);
                mloc = mn;
            }
            if ((lane & 3) == 0) {
                spm[row_l * 2 + wcol] = mloc;
                spl[row_l * 2 + wcol] = lloc;
            }
        }
    }
    __syncthreads();
    if (tid < 128) {
        float m0 = spm[tid * 2], m1 = spm[tid * 2 + 1];
        float l0 = spl[tid * 2], l1 = spl[tid * 2 + 1];
        float mn = fmaxf(m0, m1);
        float l = l0 * __expf(m0 - mn) + l1 * __expf(m1 - mn);
        size_t idx = ((size_t)b * SEQ + it * 128 + tid) * TT + jt;
        g_pm[idx] = mn;
        g_pl[idx] = l;
    }
}

// ---------------------------------------------------------------------------
// Kernel 2: chunked PV via single-pass fp16 HMMA with fused combine +
// normalize + final-W write.
// ---------------------------------------------------------------------------
__global__ __launch_bounds__(256, 2) void pv_kernel(
    const float* __restrict__ Vg, float* __restrict__ Wg)
{
    int t = blockIdx.x, b = blockIdx.y;
    int it = 0;
    while (true) { int nc = (TT - it + CH - 1) / CH; if (t < nc) break; t -= nc; ++it; }
    int chunk = t;
    int jt_begin = it + chunk * CH;
    int jt_end   = min(jt_begin + CH, TT);

    extern __shared__ char smc[];
    uint32_t sb = smem_u32(smc);
    int tid = threadIdx.x, wid = tid >> 5, lane = tid & 31;
    int m_base = (wid & 3) * 32, n_base = (wid >> 2) * 64;   // n = d
    size_t Wbb = (size_t)b * SEQ * SEQ;

    // inline combine: per local row, fold partials over jt in [it, TT)
    float* sm_m  = (float*)(smc + OFF_M);
    float* sm_li = (float*)(smc + OFF_LI);
    if (tid < 128) {
        size_t rbase = ((size_t)b * SEQ + it * 128 + tid) * TT;
        float m = -FLT_MAX, l = 0.f;
        for (int jt = it; jt < TT; jt++) {
            float mp = g_pm[rbase + jt];
            float lp = g_pl[rbase + jt];
            float mn = fmaxf(m, mp);
            l = l * __expf(m - mn) + lp * __expf(mp - mn);
            m = mn;
        }
        sm_m[tid]  = m;
        sm_li[tid] = 1.0f / l;
    }
    __syncthreads();

    float acc[2][8][4];
    #pragma unroll
    for (int mt = 0; mt < 2; mt++)
        #pragma unroll
        for (int nt = 0; nt < 8; nt++)
            #pragma unroll
            for (int e = 0; e < 4; e++) acc[mt][nt][e] = 0.f;

    for (int jt = jt_begin; jt < jt_end; jt++) {
        #pragma unroll
        for (int kc = 0; kc < 2; kc++) {
            __syncthreads();
            // stage normalized W fp16 (cols kc*64..+64), write final W to gmem
            #pragma unroll
            for (int k = 0; k < 8; k++) {
                int idx = tid + k * 256;
                int r = idx >> 4, c4 = idx & 15;
                int ig = it * 128 + r;
                int jg = jt * 128 + kc * 64 + c4 * 4;
                float mm = sm_m[r];
                float li = sm_li[r];
                float* wp = Wg + Wbb + (size_t)ig * SEQ + jg;
                float4 s = *(const float4*)wp;
                float4 w;
                w.x = (jg + 0 >= ig) ? __expf(s.x - mm) * li : 0.f;
                w.y = (jg + 1 >= ig) ? __expf(s.y - mm) * li : 0.f;
                w.z = (jg + 2 >= ig) ? __expf(s.z - mm) * li : 0.f;
                w.w = (jg + 3 >= ig) ? __expf(s.w - mm) * li : 0.f;
                *(float4*)wp = w;
                *(uint2*)(smc + OFF_WH + r * SA_STRIDE + c4 * 8) =
                    make_uint2(pack_half2(w.x, w.y), pack_half2(w.z, w.w));
            }
            // stage V fp16 rows [jt*128+kc*64, +64), row-major [j][d]
            const float* Vb = Vg + ((size_t)b * SEQ + (size_t)jt * 128 + kc * 64) * HD;
            #pragma unroll
            for (int k = 0; k < 8; k++) {
                int idx = tid + k * 256;
                int r = idx >> 5, c4 = idx & 31;
                float4 v = *(const float4*)(Vb + r * HD + c4 * 4);
                *(uint2*)(smc + OFF_VH + r * SV_STRIDE + c4 * 8) =
                    make_uint2(pack_half2(v.x, v.y), pack_half2(v.z, v.w));
            }
            __syncthreads();

            int arow = lane & 15, akg = lane >> 4;
            int jrow = (lane & 7) + (lane & 8);     // trans-B source row (k = j)
            int dcol = (lane >> 4) * 8;
            #pragma unroll
            for (int ks = 0; ks < 4; ks++) {
                uint32_t a[2][4];
                ldm_x4(a[0], sb + OFF_WH + (m_base + arow) * SA_STRIDE + (ks * 16 + akg * 8) * 2);
                ldm_x4(a[1], sb + OFF_WH + (m_base + 16 + arow) * SA_STRIDE + (ks * 16 + akg * 8) * 2);
                #pragma unroll
                for (int ntp = 0; ntp < 4; ntp++) {
                    uint32_t bf[4];
                    ldm_x4_t(bf, sb + OFF_VH + (ks * 16 + jrow) * SV_STRIDE
                                  + (n_base + ntp * 16 + dcol) * 2);
                    #pragma unroll
                    for (int mt = 0; mt < 2; mt++) {
                        mma_f16(acc[mt][ntp * 2],     a[mt], bf);
                        mma_f16(acc[mt][ntp * 2 + 1], a[mt], bf + 2);
                    }
                }
            }
        }
    }

    // write partial O tile
    float* pb = g_part + (((size_t)chunk * NB + b) * SEQ) * HD;
    int r0 = lane >> 2, c0 = (lane & 3) * 2;
    #pragma unroll
    for (int mt = 0; mt < 2; mt++) {
        #pragma unroll
        for (int nt = 0; nt < 8; nt++) {
            int i0 = it * 128 + m_base + mt * 16 + r0;
            int d  = n_base + nt * 8 + c0;
            *(float2*)(pb + (size_t)i0 * HD + d) =
                make_float2(acc[mt][nt][0], acc[mt][nt][1]);
            *(float2*)(pb + (size_t)(i0 + 8) * HD + d) =
                make_float2(acc[mt][nt][2], acc[mt][nt][3]);
        }
    }
}

// ---------------------------------------------------------------------------
// Kernel 3: reduce partials into O.
// ---------------------------------------------------------------------------
__global__ __launch_bounds__(256) void reduce_kernel(float* __restrict__ O)
{
    int idx = blockIdx.x * 256 + threadIdx.x;
    size_t base = (size_t)idx * 4;
    int row = (int)(base >> 7);
    int i   = row & (SEQ - 1);
    int it  = i >> 7;
    int nc  = (TT - it + CH - 1) / CH;

    float4 acc = make_float4(0.f, 0.f, 0.f, 0.f);
    for (int cix = 0; cix < nc; cix++) {
        const float4 p = *(const float4*)(g_part + (size_t)cix * NB * SEQ * HD + base);
        acc.x += p.x; acc.y += p.y; acc.z += p.z; acc.w += p.w;
    }
    *(float4*)(O + base) = acc;
}

// ---------------------------------------------------------------------------
extern "C" void kernel_launch(void* const* d_in, const int* in_sizes, int n_in,
                              void* d_out, int out_size)
{
    const float* Q = (const float*)d_in[0];
    const float* K = (const float*)d_in[1];
    const float* V = (const float*)d_in[2];
    float* O = (float*)d_out;                              // [NB, SEQ, HD]
    float* W = (float*)d_out + (size_t)NB * SEQ * HD;      // [NB, SEQ, SEQ]

    cudaFuncSetAttribute(scores_stats_kernel, cudaFuncAttributeMaxDynamicSharedMemorySize, SMEM_A_BYTES);
    cudaFuncSetAttribute(pv_kernel,           cudaFuncAttributeMaxDynamicSharedMemorySize, SMEM_P_BYTES);

    scores_stats_kernel<<<dim3(NPAIRS + TT, NB), 256, SMEM_A_BYTES>>>(Q, K, W);
    pv_kernel<<<dim3(NCHUNK_PAIRS, NB), 256, SMEM_P_BYTES>>>(V, W);
    reduce_kernel<<<(NB * SEQ * HD / 4) / 256, 256>>>(O);
}